// round 9
// baseline (speedup 1.0000x reference)
#include <cuda_runtime.h>
#include <cuda_fp16.h>
#include <cstdint>

// Problem constants (fixed by the dataset)
constexpr int NN   = 100000;   // nodes
constexpr int NE   = 1600000;  // edges
constexpr int NG   = 64;       // graphs
constexpr int DIN  = 128;
constexpr int DH   = 256;      // hidden == out dim

constexpr int SCHUNK = 1024;
constexpr int NBLK_SCAN = (NN + SCHUNK - 1) / SCHUNK;  // 98
constexpr int CH0 = 50048;     // chunk0 node count (391 * 128)

// Scratch (device globals — no allocations allowed)
__device__ __align__(16) float  g_dinv[NN];
__device__ __align__(16) __half g_x16[(size_t)NN * DIN]; // x' = dinv*x (fp16)
__device__ __align__(16) __half g_h [(size_t)NN * DH];   // agg outputs y1/y2 (fp16)
__device__ __align__(16) __half g_a [(size_t)NN * DH];   // GEMM1 output a1' (fp16)
__device__ __align__(16) __half g_a2[(size_t)NN * DH];   // GEMM2 output a2 (fp16)
__device__ __align__(16) __half g_wt1[DH * DIN];         // W1^T fp16 [256][128]
__device__ __align__(16) __half g_wt2[DH * DH];          // W2^T fp16 [256][256]
__device__ int g_cin [NN];
__device__ int g_off [NN];
__device__ int g_bsum[NBLK_SCAN];
__device__ int g_bsumex[NBLK_SCAN];
__device__ int g_fill[NN];
__device__ int g_adj [NE];
__device__ int g_cnt [NG];

// ---------------------------------------------------------------------------
__global__ void zero_kernel(float* __restrict__ out) {
    int i = blockIdx.x * blockDim.x + threadIdx.x;
    if (i < NN) { g_cin[i] = 0; g_fill[i] = 0; }
    if (i < NG) g_cnt[i] = 0;
    if (i < NG * DH) out[i] = 0.0f;
}

// 4 edges per thread (vectorized)
__global__ void hist_kernel(const int* __restrict__ dst) {
    int t = blockIdx.x * blockDim.x + threadIdx.x;
    if (t >= NE / 4) return;
    int4 d = reinterpret_cast<const int4*>(dst)[t];
    atomicAdd(&g_cin[d.x], 1);
    atomicAdd(&g_cin[d.y], 1);
    atomicAdd(&g_cin[d.z], 1);
    atomicAdd(&g_cin[d.w], 1);
}

// Block scan over 1024-element chunks + fused dinv computation
__global__ __launch_bounds__(256) void scan_block_kernel() {
    __shared__ int st[256];
    int base = blockIdx.x * SCHUNK;
    int tid = threadIdx.x;
    int v[4], pre[4];
    int s = 0;
#pragma unroll
    for (int i = 0; i < 4; i++) {
        int idx = base + tid * 4 + i;
        v[i] = (idx < NN) ? g_cin[idx] : 0;
        if (idx < NN) g_dinv[idx] = rsqrtf((float)(v[i] + 1));
        pre[i] = s;
        s += v[i];
    }
    st[tid] = s;
    __syncthreads();
#pragma unroll
    for (int off = 1; off < 256; off <<= 1) {
        int x = (tid >= off) ? st[tid - off] : 0;
        __syncthreads();
        st[tid] += x;
        __syncthreads();
    }
    int excl = st[tid] - s;
#pragma unroll
    for (int i = 0; i < 4; i++) {
        int idx = base + tid * 4 + i;
        if (idx < NN) g_off[idx] = excl + pre[i];
    }
    if (tid == 255) g_bsum[blockIdx.x] = st[255];
}

// Parallel exclusive scan of the 98 chunk totals (one block, 128 threads)
__global__ __launch_bounds__(128) void scan_top_kernel() {
    __shared__ int sh[128];
    int t = threadIdx.x;
    int v = (t < NBLK_SCAN) ? g_bsum[t] : 0;
    sh[t] = v;
    __syncthreads();
#pragma unroll
    for (int off = 1; off < 128; off <<= 1) {
        int x = (t >= off) ? sh[t - off] : 0;
        __syncthreads();
        sh[t] += x;
        __syncthreads();
    }
    if (t < NBLK_SCAN) g_bsumex[t] = sh[t] - v;
}

// 4 edges per thread (vectorized)
__global__ void fill_kernel(const int* __restrict__ src, const int* __restrict__ dst) {
    int t = blockIdx.x * blockDim.x + threadIdx.x;
    if (t >= NE / 4) return;
    int4 s = reinterpret_cast<const int4*>(src)[t];
    int4 d = reinterpret_cast<const int4*>(dst)[t];
    int c, pos;
    c = d.x; pos = g_off[c] + g_bsumex[c >> 10] + atomicAdd(&g_fill[c], 1); g_adj[pos] = s.x;
    c = d.y; pos = g_off[c] + g_bsumex[c >> 10] + atomicAdd(&g_fill[c], 1); g_adj[pos] = s.y;
    c = d.z; pos = g_off[c] + g_bsumex[c >> 10] + atomicAdd(&g_fill[c], 1); g_adj[pos] = s.z;
    c = d.w; pos = g_off[c] + g_bsumex[c >> 10] + atomicAdd(&g_fill[c], 1); g_adj[pos] = s.w;
}

// ---------------------------------------------------------------------------
// x (fp32) -> x' = dinv[n]*x fp16; each thread converts 8 floats
__global__ void x2h_kernel(const float* __restrict__ x) {
    int idx = blockIdx.x * blockDim.x + threadIdx.x;
    if (idx >= NN * DIN / 8) return;
    float s = g_dinv[idx >> 4];
    const float4* x4 = reinterpret_cast<const float4*>(x);
    float4 v0 = x4[idx * 2];
    float4 v1 = x4[idx * 2 + 1];
    uint4 o;
    __half2 h;
    h = __floats2half2_rn(v0.x * s, v0.y * s); o.x = *reinterpret_cast<uint32_t*>(&h);
    h = __floats2half2_rn(v0.z * s, v0.w * s); o.y = *reinterpret_cast<uint32_t*>(&h);
    h = __floats2half2_rn(v1.x * s, v1.y * s); o.z = *reinterpret_cast<uint32_t*>(&h);
    h = __floats2half2_rn(v1.z * s, v1.w * s); o.w = *reinterpret_cast<uint32_t*>(&h);
    reinterpret_cast<uint4*>(g_x16)[idx] = o;
}

// Weight transpose + fp32->fp16: Wt[n*K + k] = (half)W[k*256 + n]
__global__ void transpose_kernel(const float* __restrict__ W, __half* __restrict__ Wt, int K) {
    __shared__ float t[32][33];
    int kb = blockIdx.x * 32, nb = blockIdx.y * 32;
    int x = threadIdx.x, y = threadIdx.y;  // block (32, 8)
#pragma unroll
    for (int i = 0; i < 32; i += 8)
        t[y + i][x] = W[(size_t)(kb + y + i) * DH + nb + x];
    __syncthreads();
#pragma unroll
    for (int i = 0; i < 32; i += 8)
        Wt[(size_t)(nb + y + i) * K + kb + x] = __float2half(t[x][y + i]);
}

// ---------------------------------------------------------------------------
__device__ __forceinline__ void st_cs_v4(void* addr, uint4 v) {
    asm volatile("st.global.cs.v4.b32 [%0], {%1, %2, %3, %4};"
                 :: "l"(addr), "r"(v.x), "r"(v.y), "r"(v.z), "r"(v.w) : "memory");
}

// fp16 CSR gather over pre-scaled rows (fp32 accumulate, fp16 out):
//   y[c] = dinv[c] * ( row'[c] + sum_{r in in(c)} row'[r] )
// LPG lanes per node, 2 uint4 (16 halves) per lane. Nodes [nodeBase, nodeEnd).
template<int LPG>
__global__ __launch_bounds__(256) void agg_kernel(
    const __half* __restrict__ in, __half* __restrict__ outp,
    int nodeBase, int nodeEnd)
{
    constexpr int V4PR = 2 * LPG;
    int gtid = blockIdx.x * blockDim.x + threadIdx.x;
    int node = nodeBase + gtid / LPG;
    int lane = threadIdx.x & (LPG - 1);
    if (node >= nodeEnd) return;

    const uint4* in8 = reinterpret_cast<const uint4*>(in);
    size_t rb = (size_t)node * V4PR;

    float2 acc[2][4];
#pragma unroll
    for (int v = 0; v < 2; v++) {
        uint4 s = in8[rb + v * LPG + lane];
        const __half2* h = reinterpret_cast<const __half2*>(&s);
#pragma unroll
        for (int p = 0; p < 4; p++) acc[v][p] = __half22float2(h[p]);
    }

    int start = g_off[node] + g_bsumex[node >> 10];
    int cnt = g_cin[node];
    int j = 0;
    for (; j + 4 <= cnt; j += 4) {
        int rr[4];
#pragma unroll
        for (int u = 0; u < 4; u++) rr[u] = g_adj[start + j + u];
#pragma unroll
        for (int u = 0; u < 4; u++) {
            size_t nb = (size_t)rr[u] * V4PR;
#pragma unroll
            for (int v = 0; v < 2; v++) {
                uint4 s = in8[nb + v * LPG + lane];
                const __half2* h = reinterpret_cast<const __half2*>(&s);
#pragma unroll
                for (int p = 0; p < 4; p++) {
                    float2 f = __half22float2(h[p]);
                    acc[v][p].x += f.x;
                    acc[v][p].y += f.y;
                }
            }
        }
    }
    for (; j < cnt; j++) {
        int r0 = g_adj[start + j];
        size_t nb = (size_t)r0 * V4PR;
#pragma unroll
        for (int v = 0; v < 2; v++) {
            uint4 s = in8[nb + v * LPG + lane];
            const __half2* h = reinterpret_cast<const __half2*>(&s);
#pragma unroll
            for (int p = 0; p < 4; p++) {
                float2 f = __half22float2(h[p]);
                acc[v][p].x += f.x;
                acc[v][p].y += f.y;
            }
        }
    }

    float dc = g_dinv[node];
#pragma unroll
    for (int v = 0; v < 2; v++) {
        uint4 o;
        uint32_t* ow = &o.x;
#pragma unroll
        for (int p = 0; p < 4; p++) {
            __half2 h = __floats2half2_rn(acc[v][p].x * dc, acc[v][p].y * dc);
            ow[p] = *reinterpret_cast<uint32_t*>(&h);
        }
        __half* addr = outp + (rb + (size_t)v * LPG + lane) * 8;
        st_cs_v4(addr, o);
    }
}

// ---------------------------------------------------------------------------
// fp16 tensor-core GEMM (mma.sync m16n8k16, fp32 accumulate):
//   C[m, colBase:+128] = scale_m * relu(A[m,:K] @ Bt^T + bias), fp16 output
// Rows [row0, Mend); SCALE multiplies rows by dinv[m].
#define HPAD 40   // halves per padded smem row (80 bytes)

__device__ __forceinline__ void mma_f16(float* d, const uint32_t* a, const uint32_t* b) {
    asm volatile("mma.sync.aligned.m16n8k16.row.col.f32.f16.f16.f32 "
        "{%0,%1,%2,%3}, {%4,%5,%6,%7}, {%8,%9}, {%0,%1,%2,%3};\n"
        : "+f"(d[0]), "+f"(d[1]), "+f"(d[2]), "+f"(d[3])
        : "r"(a[0]), "r"(a[1]), "r"(a[2]), "r"(a[3]), "r"(b[0]), "r"(b[1]));
}

template<bool SCALE>
__global__ __launch_bounds__(256) void gemm_f16_kernel(
    const __half* __restrict__ A, const __half* __restrict__ Bt,
    const float* __restrict__ bias, __half* __restrict__ C,
    int row0, int Mend, int K)
{
    __shared__ __half As[2][128 * HPAD];
    __shared__ __half Bs[2][128 * HPAD];

    int tid  = threadIdx.x;
    int lane = tid & 31;
    int warp = tid >> 5;
    int warpM = warp & 1;
    int warpN = warp >> 1;
    int rowBase = row0 + blockIdx.y * 128;
    int colBase = blockIdx.x * 128;

    float acc[4][4][4];
#pragma unroll
    for (int mt = 0; mt < 4; mt++)
#pragma unroll
        for (int nt = 0; nt < 4; nt++)
#pragma unroll
            for (int i = 0; i < 4; i++) acc[mt][nt][i] = 0.0f;

    auto load_tiles = [&](int s, int k0) {
#pragma unroll
        for (int i = 0; i < 2; i++) {
            int idx = tid + i * 256;
            int row = idx >> 2;
            int c   = idx & 3;
            int gr = rowBase + row;
            const __half* srcA = A + (size_t)(gr < Mend ? gr : 0) * K + k0 + c * 8;
            uint32_t dstA = (uint32_t)__cvta_generic_to_shared(&As[s][row * HPAD + c * 8]);
            int sz = (gr < Mend) ? 16 : 0;
            asm volatile("cp.async.cg.shared.global [%0], [%1], 16, %2;\n"
                         :: "r"(dstA), "l"(srcA), "r"(sz));
            const __half* srcB = Bt + (size_t)(colBase + row) * K + k0 + c * 8;
            uint32_t dstB = (uint32_t)__cvta_generic_to_shared(&Bs[s][row * HPAD + c * 8]);
            asm volatile("cp.async.cg.shared.global [%0], [%1], 16;\n"
                         :: "r"(dstB), "l"(srcB));
        }
    };

    int r = lane >> 2;
    int kq = (lane & 3) * 2;

    auto compute = [&](int s) {
#pragma unroll
        for (int kg = 0; kg < 2; kg++) {
            int kb = kg * 16;
            uint32_t af[4][4], bf[4][2];
#pragma unroll
            for (int mt = 0; mt < 4; mt++) {
                int mb = warpM * 64 + mt * 16;
                const __half* base = &As[s][0];
                af[mt][0] = *reinterpret_cast<const uint32_t*>(base + (mb + r)     * HPAD + kb + kq);
                af[mt][1] = *reinterpret_cast<const uint32_t*>(base + (mb + r + 8) * HPAD + kb + kq);
                af[mt][2] = *reinterpret_cast<const uint32_t*>(base + (mb + r)     * HPAD + kb + kq + 8);
                af[mt][3] = *reinterpret_cast<const uint32_t*>(base + (mb + r + 8) * HPAD + kb + kq + 8);
            }
#pragma unroll
            for (int nt = 0; nt < 4; nt++) {
                int nb = warpN * 32 + nt * 8;
                const __half* base = &Bs[s][0];
                bf[nt][0] = *reinterpret_cast<const uint32_t*>(base + (nb + r) * HPAD + kb + kq);
                bf[nt][1] = *reinterpret_cast<const uint32_t*>(base + (nb + r) * HPAD + kb + kq + 8);
            }
#pragma unroll
            for (int mt = 0; mt < 4; mt++)
#pragma unroll
                for (int nt = 0; nt < 4; nt++)
                    mma_f16(acc[mt][nt], af[mt], bf[nt]);
        }
    };

    load_tiles(0, 0);
    asm volatile("cp.async.commit_group;\n");
    int buf = 0;
    for (int k0 = 32; k0 < K; k0 += 32) {
        load_tiles(buf ^ 1, k0);
        asm volatile("cp.async.commit_group;\n");
        asm volatile("cp.async.wait_group 1;\n");
        __syncthreads();
        compute(buf);
        __syncthreads();
        buf ^= 1;
    }
    asm volatile("cp.async.wait_group 0;\n");
    __syncthreads();
    compute(buf);

    int c2 = (lane & 3) * 2;
    float2 bb[4];
#pragma unroll
    for (int nt = 0; nt < 4; nt++) {
        int gcol = colBase + warpN * 32 + nt * 8 + c2;
        bb[nt] = *reinterpret_cast<const float2*>(bias + gcol);
    }
#pragma unroll
    for (int mt = 0; mt < 4; mt++) {
        int grow0 = rowBase + warpM * 64 + mt * 16 + r;
        int grow1 = grow0 + 8;
        float s0 = 1.0f, s1 = 1.0f;
        if (SCALE) {
            s0 = (grow0 < Mend) ? g_dinv[grow0] : 1.0f;
            s1 = (grow1 < Mend) ? g_dinv[grow1] : 1.0f;
        }
#pragma unroll
        for (int nt = 0; nt < 4; nt++) {
            int gcol = colBase + warpN * 32 + nt * 8 + c2;
            if (grow0 < Mend) {
                __half2 h = __floats2half2_rn(fmaxf(acc[mt][nt][0] + bb[nt].x, 0.f) * s0,
                                              fmaxf(acc[mt][nt][1] + bb[nt].y, 0.f) * s0);
                *reinterpret_cast<uint32_t*>(C + (size_t)grow0 * DH + gcol) =
                    *reinterpret_cast<uint32_t*>(&h);
            }
            if (grow1 < Mend) {
                __half2 h = __floats2half2_rn(fmaxf(acc[mt][nt][2] + bb[nt].x, 0.f) * s1,
                                              fmaxf(acc[mt][nt][3] + bb[nt].y, 0.f) * s1);
                *reinterpret_cast<uint32_t*>(C + (size_t)grow1 * DH + gcol) =
                    *reinterpret_cast<uint32_t*>(&h);
            }
        }
    }
}

// ---------------------------------------------------------------------------
// Sorted-batch pool over fp16 a2; 128 threads = 128 half2 columns, fp32 accum.
#define POOL_CHUNK 128
__global__ __launch_bounds__(128) void pool_kernel(
    const int* __restrict__ batch, const __half* __restrict__ a, float* __restrict__ out)
{
    __shared__ int sb[POOL_CHUNK];
    int start = blockIdx.x * POOL_CHUNK;
    int cnt = min(POOL_CHUNK, NN - start);
    for (int i = threadIdx.x; i < cnt; i += 128) sb[i] = batch[start + i];
    __syncthreads();

    int d = threadIdx.x;
    const __half2* a2 = reinterpret_cast<const __half2*>(a);
    int curg = sb[0];
    float ax = 0.f, ay = 0.f;
    int run = 0;
    for (int n = 0; n < cnt; n++) {
        int g = sb[n];
        if (g != curg) {
            atomicAdd(&out[curg * DH + 2 * d], ax);
            atomicAdd(&out[curg * DH + 2 * d + 1], ay);
            if (d == 0) atomicAdd(&g_cnt[curg], run);
            ax = 0.f; ay = 0.f; run = 0; curg = g;
        }
        float2 f = __half22float2(a2[(size_t)(start + n) * 128 + d]);
        ax += f.x; ay += f.y;
        run++;
    }
    atomicAdd(&out[curg * DH + 2 * d], ax);
    atomicAdd(&out[curg * DH + 2 * d + 1], ay);
    if (d == 0) atomicAdd(&g_cnt[curg], run);
}

__global__ void divide_kernel(float* __restrict__ out) {
    int idx = blockIdx.x * blockDim.x + threadIdx.x;
    if (idx >= NG * DH) return;
    int g = idx >> 8;
    float c = (float)g_cnt[g];
    out[idx] = out[idx] / fmaxf(c, 1.0f);
}

// ---------------------------------------------------------------------------
extern "C" void kernel_launch(void* const* d_in, const int* in_sizes, int n_in,
                              void* d_out, int out_size)
{
    const float* x    = (const float*)d_in[0];
    const int*   ei   = (const int*)  d_in[1];
    const int*   batch= (const int*)  d_in[2];
    const float* W1   = (const float*)d_in[3];
    const float* b1   = (const float*)d_in[4];
    const float* W2   = (const float*)d_in[5];
    const float* b2   = (const float*)d_in[6];
    float* out = (float*)d_out;

    const int* src = ei;
    const int* dst = ei + NE;

    __half* d_x16; cudaGetSymbolAddress((void**)&d_x16, g_x16);
    __half* d_h;   cudaGetSymbolAddress((void**)&d_h, g_h);
    __half* d_a;   cudaGetSymbolAddress((void**)&d_a, g_a);
    __half* d_a2;  cudaGetSymbolAddress((void**)&d_a2, g_a2);
    __half* d_wt1; cudaGetSymbolAddress((void**)&d_wt1, g_wt1);
    __half* d_wt2; cudaGetSymbolAddress((void**)&d_wt2, g_wt2);

    // Lazy one-time stream/event setup (first call is the un-captured
    // correctness run; capture calls only record/wait).
    static cudaStream_t s1 = nullptr;
    static cudaEvent_t ev[10];
    if (!s1) {
        cudaStreamCreateWithFlags(&s1, cudaStreamNonBlocking);
        for (int i = 0; i < 10; i++)
            cudaEventCreateWithFlags(&ev[i], cudaEventDisableTiming);
    }

    // ---- fork: weight transposes on s1; CSR build on main ----
    cudaEventRecord(ev[0], 0);
    cudaStreamWaitEvent(s1, ev[0], 0);
    transpose_kernel<<<dim3(DIN / 32, DH / 32), dim3(32, 8), 0, s1>>>(W1, d_wt1, DIN);
    transpose_kernel<<<dim3(DH / 32, DH / 32), dim3(32, 8), 0, s1>>>(W2, d_wt2, DH);

    zero_kernel<<<(NN + 255) / 256, 256>>>(out);
    hist_kernel<<<(NE / 4 + 255) / 256, 256>>>(dst);
    scan_block_kernel<<<NBLK_SCAN, 256>>>();
    cudaEventRecord(ev[1], 0);                 // dinv ready
    scan_top_kernel<<<1, 128>>>();
    fill_kernel<<<(NE / 4 + 255) / 256, 256>>>(src, dst);

    cudaStreamWaitEvent(s1, ev[1], 0);
    x2h_kernel<<<(NN * DIN / 8 + 255) / 256, 256, 0, s1>>>(x);   // needs dinv
    cudaEventRecord(ev[2], s1);
    cudaStreamWaitEvent(0, ev[2], 0);          // join: x16 + weights ready

    dim3 gGrid(2, 391);   // per-chunk GEMM grid (both chunks: 391 row-blocks)

    // ---- Layer 1 (pipelined 2 chunks): agg on main, GEMM on s1 ----
    agg_kernel<8><<<(CH0 * 8 + 255) / 256, 256>>>(d_x16, d_h, 0, CH0);
    cudaEventRecord(ev[3], 0);
    cudaStreamWaitEvent(s1, ev[3], 0);
    gemm_f16_kernel<true><<<gGrid, 256, 0, s1>>>(d_h, d_wt1, b1, d_a, 0, CH0, DIN);
    agg_kernel<8><<<((NN - CH0) * 8 + 255) / 256, 256>>>(d_x16, d_h, CH0, NN);
    cudaEventRecord(ev[4], 0);
    cudaStreamWaitEvent(s1, ev[4], 0);
    gemm_f16_kernel<true><<<gGrid, 256, 0, s1>>>(d_h, d_wt1, b1, d_a, CH0, NN, DIN);
    cudaEventRecord(ev[5], s1);
    cudaStreamWaitEvent(0, ev[5], 0);          // a1' fully ready

    // ---- Layer 2 (pipelined 2 chunks): GEMM writes separate a2 buffer ----
    agg_kernel<16><<<(CH0 * 16 + 255) / 256, 256>>>(d_a, d_h, 0, CH0);
    cudaEventRecord(ev[6], 0);
    cudaStreamWaitEvent(s1, ev[6], 0);
    gemm_f16_kernel<false><<<gGrid, 256, 0, s1>>>(d_h, d_wt2, b2, d_a2, 0, CH0, DH);
    agg_kernel<16><<<((NN - CH0) * 16 + 255) / 256, 256>>>(d_a, d_h, CH0, NN);
    cudaEventRecord(ev[7], 0);
    cudaStreamWaitEvent(s1, ev[7], 0);
    gemm_f16_kernel<false><<<gGrid, 256, 0, s1>>>(d_h, d_wt2, b2, d_a2, CH0, NN, DH);
    cudaEventRecord(ev[8], s1);
    cudaStreamWaitEvent(0, ev[8], 0);

    // ---- Global mean pool ----
    pool_kernel<<<(NN + POOL_CHUNK - 1) / POOL_CHUNK, 128>>>(batch, d_a2, out);
    divide_kernel<<<(NG * DH + 255) / 256, 256>>>(out);
}

// round 11
// speedup vs baseline: 1.1540x; 1.1540x over previous
#include <cuda_runtime.h>
#include <cuda_fp16.h>
#include <cstdint>

// Problem constants (fixed by the dataset)
constexpr int NN   = 100000;   // nodes
constexpr int NE   = 1600000;  // edges
constexpr int NG   = 64;       // graphs
constexpr int DIN  = 128;
constexpr int DH   = 256;      // hidden == out dim

constexpr int SCHUNK = 1024;
constexpr int NBLK_SCAN = (NN + SCHUNK - 1) / SCHUNK;  // 98

// Scratch (device globals — no allocations allowed)
__device__ __align__(16) float  g_dinv[NN];
__device__ __align__(16) __half g_x16[(size_t)NN * DIN]; // x' = dinv*x (fp16)
__device__ __align__(16) __half g_h [(size_t)NN * DH];   // agg outputs y1/y2 (fp16)
__device__ __align__(16) __half g_a [(size_t)NN * DH];   // GEMM outputs a1'/a2 (fp16)
__device__ __align__(16) __half g_wt1[DH * DIN];         // W1^T fp16 [256][128]
__device__ __align__(16) __half g_wt2[DH * DH];          // W2^T fp16 [256][256]
__device__ int g_cin [NN];
__device__ int g_off [NN];
__device__ int g_bsum[NBLK_SCAN];
__device__ int g_bsumex[NBLK_SCAN];
__device__ int g_fill[NN];
__device__ int g_adj [NE];
__device__ int g_cnt [NG];

// ---------------------------------------------------------------------------
__global__ void zero_kernel(float* __restrict__ out) {
    int i = blockIdx.x * blockDim.x + threadIdx.x;
    if (i < NN) { g_cin[i] = 0; g_fill[i] = 0; }
    if (i < NG) g_cnt[i] = 0;
    if (i < NG * DH) out[i] = 0.0f;
}

// 4 edges per thread (vectorized)
__global__ void hist_kernel(const int* __restrict__ dst) {
    int t = blockIdx.x * blockDim.x + threadIdx.x;
    if (t >= NE / 4) return;
    int4 d = reinterpret_cast<const int4*>(dst)[t];
    atomicAdd(&g_cin[d.x], 1);
    atomicAdd(&g_cin[d.y], 1);
    atomicAdd(&g_cin[d.z], 1);
    atomicAdd(&g_cin[d.w], 1);
}

// Block scan over 1024-element chunks + fused dinv computation
__global__ __launch_bounds__(256) void scan_block_kernel() {
    __shared__ int st[256];
    int base = blockIdx.x * SCHUNK;
    int tid = threadIdx.x;
    int v[4], pre[4];
    int s = 0;
#pragma unroll
    for (int i = 0; i < 4; i++) {
        int idx = base + tid * 4 + i;
        v[i] = (idx < NN) ? g_cin[idx] : 0;
        if (idx < NN) g_dinv[idx] = rsqrtf((float)(v[i] + 1));
        pre[i] = s;
        s += v[i];
    }
    st[tid] = s;
    __syncthreads();
#pragma unroll
    for (int off = 1; off < 256; off <<= 1) {
        int x = (tid >= off) ? st[tid - off] : 0;
        __syncthreads();
        st[tid] += x;
        __syncthreads();
    }
    int excl = st[tid] - s;
#pragma unroll
    for (int i = 0; i < 4; i++) {
        int idx = base + tid * 4 + i;
        if (idx < NN) g_off[idx] = excl + pre[i];
    }
    if (tid == 255) g_bsum[blockIdx.x] = st[255];
}

// Parallel exclusive scan of the 98 chunk totals (one block, 128 threads)
__global__ __launch_bounds__(128) void scan_top_kernel() {
    __shared__ int sh[128];
    int t = threadIdx.x;
    int v = (t < NBLK_SCAN) ? g_bsum[t] : 0;
    sh[t] = v;
    __syncthreads();
#pragma unroll
    for (int off = 1; off < 128; off <<= 1) {
        int x = (t >= off) ? sh[t - off] : 0;
        __syncthreads();
        sh[t] += x;
        __syncthreads();
    }
    if (t < NBLK_SCAN) g_bsumex[t] = sh[t] - v;
}

// 4 edges per thread (vectorized)
__global__ void fill_kernel(const int* __restrict__ src, const int* __restrict__ dst) {
    int t = blockIdx.x * blockDim.x + threadIdx.x;
    if (t >= NE / 4) return;
    int4 s = reinterpret_cast<const int4*>(src)[t];
    int4 d = reinterpret_cast<const int4*>(dst)[t];
    int c, pos;
    c = d.x; pos = g_off[c] + g_bsumex[c >> 10] + atomicAdd(&g_fill[c], 1); g_adj[pos] = s.x;
    c = d.y; pos = g_off[c] + g_bsumex[c >> 10] + atomicAdd(&g_fill[c], 1); g_adj[pos] = s.y;
    c = d.z; pos = g_off[c] + g_bsumex[c >> 10] + atomicAdd(&g_fill[c], 1); g_adj[pos] = s.z;
    c = d.w; pos = g_off[c] + g_bsumex[c >> 10] + atomicAdd(&g_fill[c], 1); g_adj[pos] = s.w;
}

// ---------------------------------------------------------------------------
// x (fp32) -> x' = dinv[n]*x fp16; each thread converts 8 floats
__global__ void x2h_kernel(const float* __restrict__ x) {
    int idx = blockIdx.x * blockDim.x + threadIdx.x;
    if (idx >= NN * DIN / 8) return;
    float s = g_dinv[idx >> 4];
    const float4* x4 = reinterpret_cast<const float4*>(x);
    float4 v0 = x4[idx * 2];
    float4 v1 = x4[idx * 2 + 1];
    uint4 o;
    __half2 h;
    h = __floats2half2_rn(v0.x * s, v0.y * s); o.x = *reinterpret_cast<uint32_t*>(&h);
    h = __floats2half2_rn(v0.z * s, v0.w * s); o.y = *reinterpret_cast<uint32_t*>(&h);
    h = __floats2half2_rn(v1.x * s, v1.y * s); o.z = *reinterpret_cast<uint32_t*>(&h);
    h = __floats2half2_rn(v1.z * s, v1.w * s); o.w = *reinterpret_cast<uint32_t*>(&h);
    reinterpret_cast<uint4*>(g_x16)[idx] = o;
}

// Weight transpose + fp32->fp16: Wt[n*K + k] = (half)W[k*256 + n]
__global__ void transpose_kernel(const float* __restrict__ W, __half* __restrict__ Wt, int K) {
    __shared__ float t[32][33];
    int kb = blockIdx.x * 32, nb = blockIdx.y * 32;
    int x = threadIdx.x, y = threadIdx.y;  // block (32, 8)
#pragma unroll
    for (int i = 0; i < 32; i += 8)
        t[y + i][x] = W[(size_t)(kb + y + i) * DH + nb + x];
    __syncthreads();
#pragma unroll
    for (int i = 0; i < 32; i += 8)
        Wt[(size_t)(nb + y + i) * K + kb + x] = __float2half(t[x][y + i]);
}

// ---------------------------------------------------------------------------
__device__ __forceinline__ void st_cs_v4(void* addr, uint4 v) {
    asm volatile("st.global.cs.v4.b32 [%0], {%1, %2, %3, %4};"
                 :: "l"(addr), "r"(v.x), "r"(v.y), "r"(v.z), "r"(v.w) : "memory");
}

// fp16 CSR gather over pre-scaled rows (fp32 accumulate, fp16 out):
//   y[c] = dinv[c] * ( row'[c] + sum_{r in in(c)} row'[r] )
// LPG lanes per node, 2 uint4 (16 halves) per lane.
template<int LPG>
__global__ __launch_bounds__(256) void agg_kernel(
    const __half* __restrict__ in, __half* __restrict__ outp)
{
    constexpr int V4PR = 2 * LPG;   // uint4 per row (16 -> D=128, 32 -> D=256)
    int gtid = blockIdx.x * blockDim.x + threadIdx.x;
    int node = gtid / LPG;
    int lane = threadIdx.x & (LPG - 1);
    if (node >= NN) return;

    const uint4* in8 = reinterpret_cast<const uint4*>(in);
    size_t rb = (size_t)node * V4PR;

    float2 acc[2][4];
#pragma unroll
    for (int v = 0; v < 2; v++) {
        uint4 s = in8[rb + v * LPG + lane];
        const __half2* h = reinterpret_cast<const __half2*>(&s);
#pragma unroll
        for (int p = 0; p < 4; p++) acc[v][p] = __half22float2(h[p]);
    }

    int start = g_off[node] + g_bsumex[node >> 10];
    int cnt = g_cin[node];
    int j = 0;
    for (; j + 4 <= cnt; j += 4) {
        int rr[4];
#pragma unroll
        for (int u = 0; u < 4; u++) rr[u] = g_adj[start + j + u];
#pragma unroll
        for (int u = 0; u < 4; u++) {
            size_t nb = (size_t)rr[u] * V4PR;
#pragma unroll
            for (int v = 0; v < 2; v++) {
                uint4 s = in8[nb + v * LPG + lane];
                const __half2* h = reinterpret_cast<const __half2*>(&s);
#pragma unroll
                for (int p = 0; p < 4; p++) {
                    float2 f = __half22float2(h[p]);
                    acc[v][p].x += f.x;
                    acc[v][p].y += f.y;
                }
            }
        }
    }
    for (; j < cnt; j++) {
        int r0 = g_adj[start + j];
        size_t nb = (size_t)r0 * V4PR;
#pragma unroll
        for (int v = 0; v < 2; v++) {
            uint4 s = in8[nb + v * LPG + lane];
            const __half2* h = reinterpret_cast<const __half2*>(&s);
#pragma unroll
            for (int p = 0; p < 4; p++) {
                float2 f = __half22float2(h[p]);
                acc[v][p].x += f.x;
                acc[v][p].y += f.y;
            }
        }
    }

    float dc = g_dinv[node];
#pragma unroll
    for (int v = 0; v < 2; v++) {
        uint4 o;
        uint32_t* ow = &o.x;
#pragma unroll
        for (int p = 0; p < 4; p++) {
            __half2 h = __floats2half2_rn(acc[v][p].x * dc, acc[v][p].y * dc);
            ow[p] = *reinterpret_cast<uint32_t*>(&h);
        }
        __half* addr = outp + (rb + (size_t)v * LPG + lane) * 8;
        st_cs_v4(addr, o);
    }
}

// ---------------------------------------------------------------------------
// fp16 tensor-core GEMM (mma.sync m16n8k16, fp32 accumulate):
//   C[m, colBase:+128] = scale_m * relu(A[m,:K] @ Bt^T + bias), fp16 output
#define HPAD 40   // halves per padded smem row (80 bytes)

__device__ __forceinline__ void mma_f16(float* d, const uint32_t* a, const uint32_t* b) {
    asm volatile("mma.sync.aligned.m16n8k16.row.col.f32.f16.f16.f32 "
        "{%0,%1,%2,%3}, {%4,%5,%6,%7}, {%8,%9}, {%0,%1,%2,%3};\n"
        : "+f"(d[0]), "+f"(d[1]), "+f"(d[2]), "+f"(d[3])
        : "r"(a[0]), "r"(a[1]), "r"(a[2]), "r"(a[3]), "r"(b[0]), "r"(b[1]));
}

template<bool SCALE>
__global__ __launch_bounds__(256) void gemm_f16_kernel(
    const __half* __restrict__ A, const __half* __restrict__ Bt,
    const float* __restrict__ bias, __half* __restrict__ C,
    int M, int K)
{
    __shared__ __half As[2][128 * HPAD];
    __shared__ __half Bs[2][128 * HPAD];

    int tid  = threadIdx.x;
    int lane = tid & 31;
    int warp = tid >> 5;
    int warpM = warp & 1;
    int warpN = warp >> 1;
    int rowBase = blockIdx.y * 128;
    int colBase = blockIdx.x * 128;

    float acc[4][4][4];
#pragma unroll
    for (int mt = 0; mt < 4; mt++)
#pragma unroll
        for (int nt = 0; nt < 4; nt++)
#pragma unroll
            for (int i = 0; i < 4; i++) acc[mt][nt][i] = 0.0f;

    auto load_tiles = [&](int s, int k0) {
#pragma unroll
        for (int i = 0; i < 2; i++) {
            int idx = tid + i * 256;
            int row = idx >> 2;
            int c   = idx & 3;
            int gr = rowBase + row;
            const __half* srcA = A + (size_t)(gr < M ? gr : 0) * K + k0 + c * 8;
            uint32_t dstA = (uint32_t)__cvta_generic_to_shared(&As[s][row * HPAD + c * 8]);
            int sz = (gr < M) ? 16 : 0;
            asm volatile("cp.async.cg.shared.global [%0], [%1], 16, %2;\n"
                         :: "r"(dstA), "l"(srcA), "r"(sz));
            const __half* srcB = Bt + (size_t)(colBase + row) * K + k0 + c * 8;
            uint32_t dstB = (uint32_t)__cvta_generic_to_shared(&Bs[s][row * HPAD + c * 8]);
            asm volatile("cp.async.cg.shared.global [%0], [%1], 16;\n"
                         :: "r"(dstB), "l"(srcB));
        }
    };

    int r = lane >> 2;
    int kq = (lane & 3) * 2;

    auto compute = [&](int s) {
#pragma unroll
        for (int kg = 0; kg < 2; kg++) {
            int kb = kg * 16;
            uint32_t af[4][4], bf[4][2];
#pragma unroll
            for (int mt = 0; mt < 4; mt++) {
                int mb = warpM * 64 + mt * 16;
                const __half* base = &As[s][0];
                af[mt][0] = *reinterpret_cast<const uint32_t*>(base + (mb + r)     * HPAD + kb + kq);
                af[mt][1] = *reinterpret_cast<const uint32_t*>(base + (mb + r + 8) * HPAD + kb + kq);
                af[mt][2] = *reinterpret_cast<const uint32_t*>(base + (mb + r)     * HPAD + kb + kq + 8);
                af[mt][3] = *reinterpret_cast<const uint32_t*>(base + (mb + r + 8) * HPAD + kb + kq + 8);
            }
#pragma unroll
            for (int nt = 0; nt < 4; nt++) {
                int nb = warpN * 32 + nt * 8;
                const __half* base = &Bs[s][0];
                bf[nt][0] = *reinterpret_cast<const uint32_t*>(base + (nb + r) * HPAD + kb + kq);
                bf[nt][1] = *reinterpret_cast<const uint32_t*>(base + (nb + r) * HPAD + kb + kq + 8);
            }
#pragma unroll
            for (int mt = 0; mt < 4; mt++)
#pragma unroll
                for (int nt = 0; nt < 4; nt++)
                    mma_f16(acc[mt][nt], af[mt], bf[nt]);
        }
    };

    load_tiles(0, 0);
    asm volatile("cp.async.commit_group;\n");
    int buf = 0;
    for (int k0 = 32; k0 < K; k0 += 32) {
        load_tiles(buf ^ 1, k0);
        asm volatile("cp.async.commit_group;\n");
        asm volatile("cp.async.wait_group 1;\n");
        __syncthreads();
        compute(buf);
        __syncthreads();
        buf ^= 1;
    }
    asm volatile("cp.async.wait_group 0;\n");
    __syncthreads();
    compute(buf);

    int c2 = (lane & 3) * 2;
    float2 bb[4];
#pragma unroll
    for (int nt = 0; nt < 4; nt++) {
        int gcol = colBase + warpN * 32 + nt * 8 + c2;
        bb[nt] = *reinterpret_cast<const float2*>(bias + gcol);
    }
#pragma unroll
    for (int mt = 0; mt < 4; mt++) {
        int grow0 = rowBase + warpM * 64 + mt * 16 + r;
        int grow1 = grow0 + 8;
        float s0 = 1.0f, s1 = 1.0f;
        if (SCALE) {
            s0 = (grow0 < M) ? g_dinv[grow0] : 1.0f;
            s1 = (grow1 < M) ? g_dinv[grow1] : 1.0f;
        }
#pragma unroll
        for (int nt = 0; nt < 4; nt++) {
            int gcol = colBase + warpN * 32 + nt * 8 + c2;
            if (grow0 < M) {
                __half2 h = __floats2half2_rn(fmaxf(acc[mt][nt][0] + bb[nt].x, 0.f) * s0,
                                              fmaxf(acc[mt][nt][1] + bb[nt].y, 0.f) * s0);
                *reinterpret_cast<uint32_t*>(C + (size_t)grow0 * DH + gcol) =
                    *reinterpret_cast<uint32_t*>(&h);
            }
            if (grow1 < M) {
                __half2 h = __floats2half2_rn(fmaxf(acc[mt][nt][2] + bb[nt].x, 0.f) * s1,
                                              fmaxf(acc[mt][nt][3] + bb[nt].y, 0.f) * s1);
                *reinterpret_cast<uint32_t*>(C + (size_t)grow1 * DH + gcol) =
                    *reinterpret_cast<uint32_t*>(&h);
            }
        }
    }
}

// ---------------------------------------------------------------------------
// Sorted-batch pool over fp16 a2; 128 threads = 128 half2 columns, fp32 accum.
#define POOL_CHUNK 64
__global__ __launch_bounds__(128) void pool_kernel(
    const int* __restrict__ batch, const __half* __restrict__ a, float* __restrict__ out)
{
    __shared__ int sb[POOL_CHUNK];
    int start = blockIdx.x * POOL_CHUNK;
    int cnt = min(POOL_CHUNK, NN - start);
    for (int i = threadIdx.x; i < cnt; i += 128) sb[i] = batch[start + i];
    __syncthreads();

    int d = threadIdx.x;
    const __half2* a2 = reinterpret_cast<const __half2*>(a);
    int curg = sb[0];
    float ax = 0.f, ay = 0.f;
    int run = 0;
    for (int n = 0; n < cnt; n++) {
        int g = sb[n];
        if (g != curg) {
            atomicAdd(&out[curg * DH + 2 * d], ax);
            atomicAdd(&out[curg * DH + 2 * d + 1], ay);
            if (d == 0) atomicAdd(&g_cnt[curg], run);
            ax = 0.f; ay = 0.f; run = 0; curg = g;
        }
        float2 f = __half22float2(a2[(size_t)(start + n) * 128 + d]);
        ax += f.x; ay += f.y;
        run++;
    }
    atomicAdd(&out[curg * DH + 2 * d], ax);
    atomicAdd(&out[curg * DH + 2 * d + 1], ay);
    if (d == 0) atomicAdd(&g_cnt[curg], run);
}

__global__ void divide_kernel(float* __restrict__ out) {
    int idx = blockIdx.x * blockDim.x + threadIdx.x;
    if (idx >= NG * DH) return;
    int g = idx >> 8;
    float c = (float)g_cnt[g];
    out[idx] = out[idx] / fmaxf(c, 1.0f);
}

// ---------------------------------------------------------------------------
extern "C" void kernel_launch(void* const* d_in, const int* in_sizes, int n_in,
                              void* d_out, int out_size)
{
    const float* x    = (const float*)d_in[0];
    const int*   ei   = (const int*)  d_in[1];
    const int*   batch= (const int*)  d_in[2];
    const float* W1   = (const float*)d_in[3];
    const float* b1   = (const float*)d_in[4];
    const float* W2   = (const float*)d_in[5];
    const float* b2   = (const float*)d_in[6];
    float* out = (float*)d_out;

    const int* src = ei;
    const int* dst = ei + NE;

    __half* d_x16; cudaGetSymbolAddress((void**)&d_x16, g_x16);
    __half* d_h;   cudaGetSymbolAddress((void**)&d_h, g_h);
    __half* d_a;   cudaGetSymbolAddress((void**)&d_a, g_a);
    __half* d_wt1; cudaGetSymbolAddress((void**)&d_wt1, g_wt1);
    __half* d_wt2; cudaGetSymbolAddress((void**)&d_wt2, g_wt2);

    // Lazy one-time stream/event setup (first call is the un-captured
    // correctness run; capture calls only record/wait).
    static cudaStream_t s1 = nullptr;
    static cudaEvent_t ev[3];
    if (!s1) {
        cudaStreamCreateWithFlags(&s1, cudaStreamNonBlocking);
        for (int i = 0; i < 3; i++)
            cudaEventCreateWithFlags(&ev[i], cudaEventDisableTiming);
    }

    // ---- fork: weight transposes + x2h on s1; CSR build on main ----
    cudaEventRecord(ev[0], 0);
    cudaStreamWaitEvent(s1, ev[0], 0);
    transpose_kernel<<<dim3(DIN / 32, DH / 32), dim3(32, 8), 0, s1>>>(W1, d_wt1, DIN);
    transpose_kernel<<<dim3(DH / 32, DH / 32), dim3(32, 8), 0, s1>>>(W2, d_wt2, DH);

    zero_kernel<<<(NN + 255) / 256, 256>>>(out);
    hist_kernel<<<(NE / 4 + 255) / 256, 256>>>(dst);
    scan_block_kernel<<<NBLK_SCAN, 256>>>();
    cudaEventRecord(ev[1], 0);                 // dinv ready
    scan_top_kernel<<<1, 128>>>();
    fill_kernel<<<(NE / 4 + 255) / 256, 256>>>(src, dst);

    cudaStreamWaitEvent(s1, ev[1], 0);
    x2h_kernel<<<(NN * DIN / 8 + 255) / 256, 256, 0, s1>>>(x);   // needs dinv
    cudaEventRecord(ev[2], s1);
    cudaStreamWaitEvent(0, ev[2], 0);          // join: x16 + weights ready

    dim3 gemmGrid(2, (NN + 127) / 128);   // (2, 782)

    // ---- Layer 1: agg(x') D=128, GEMM fp16 -> a1' = dinv*relu(...) ----
    agg_kernel<8><<<(NN * 8 + 255) / 256, 256>>>(d_x16, d_h);
    gemm_f16_kernel<true><<<gemmGrid, 256>>>(d_h, d_wt1, b1, d_a, NN, DIN);

    // ---- Layer 2: agg(a1') D=256, GEMM fp16 -> a2 ----
    agg_kernel<16><<<(NN * 16 + 255) / 256, 256>>>(d_a, d_h);
    gemm_f16_kernel<false><<<gemmGrid, 256>>>(d_h, d_wt2, b2, d_a, NN, DH);

    // ---- Global mean pool ----
    pool_kernel<<<(NN + POOL_CHUNK - 1) / POOL_CHUNK, 128>>>(batch, d_a, out);
    divide_kernel<<<(NG * DH + 255) / 256, 256>>>(out);
}